// round 10
// baseline (speedup 1.0000x reference)
#include <cuda_runtime.h>
#include <math.h>

#define IN_CH   64
#define MID     128      // OUT_CH*HEADS
#define GH      256      // HEADS*IN_CH (gate hidden)
#define HEADS   4
#define SEGS    1024
#define MAXN    500000
#define MAXLOC  8

// scratch (static device globals — no runtime allocation)
__device__ float g_gate[(size_t)MAXN * HEADS];   // 8 MB
__device__ float g_denom[SEGS * HEADS];

// ------------------------------------------------------------------
// init: zero output accumulator and denominators
// ------------------------------------------------------------------
__global__ void k_init(float* __restrict__ out) {
    int i = blockIdx.x * blockDim.x + threadIdx.x;
    if (i < SEGS * MID)   out[i] = 0.f;
    if (i < SEGS * HEADS) g_denom[i] = 0.f;
}

// ------------------------------------------------------------------
// Pass A: gate[N,4] = prelu(x @ gw1^T) @ gw2^T
// block = 64 nodes, 256 threads, C tile [64 x 256] (8x8 micro per thread)
// smem: xs[64][65] | w1[256][65] | w2[4*256]
// ------------------------------------------------------------------
#define A_SMEM_FLOATS (64*65 + 256*65 + 1024)
__global__ __launch_bounds__(256) void k_gate(
    const float* __restrict__ x, const float* __restrict__ gw1,
    const float* __restrict__ gw2, const float* __restrict__ prelu_a, int n)
{
    extern __shared__ float sm[];
    float* xs  = sm;                    // 64*65 = 4160
    float* w1s = sm + 4160;             // 256*65 = 16640
    float* w2s = sm + 4160 + 16640;     // 1024

    int tid = threadIdx.x;
    int m0  = blockIdx.x * 64;

    {   // x tile (zero padded)
        const float4* x4 = (const float4*)x;
        #pragma unroll
        for (int t = 0; t < 4; ++t) {
            int fid = tid + t * 256;            // < 1024
            int m = fid >> 4, k4 = fid & 15;
            float4 v = make_float4(0.f, 0.f, 0.f, 0.f);
            if (m0 + m < n) v = x4[(size_t)(m0 + m) * 16 + k4];
            float* d = &xs[m * 65 + k4 * 4];
            d[0] = v.x; d[1] = v.y; d[2] = v.z; d[3] = v.w;
        }
        const float4* w14 = (const float4*)gw1;
        #pragma unroll
        for (int t = 0; t < 16; ++t) {
            int fid = tid + t * 256;            // < 4096
            int c = fid >> 4, k4 = fid & 15;
            float4 v = w14[fid];
            float* d = &w1s[c * 65 + k4 * 4];
            d[0] = v.x; d[1] = v.y; d[2] = v.z; d[3] = v.w;
        }
        ((float4*)w2s)[tid] = ((const float4*)gw2)[tid];  // 256 float4 = 1024 f
    }
    __syncthreads();

    int rg = tid >> 5, cg = tid & 31;   // warp = one row-group, lanes span cols
    int r0 = rg * 8, c0 = cg * 4;

    float acc[8][8];
    #pragma unroll
    for (int i = 0; i < 8; ++i)
        #pragma unroll
        for (int j = 0; j < 8; ++j) acc[i][j] = 0.f;

    #pragma unroll 8
    for (int k = 0; k < 64; ++k) {
        float a[8], b[8];
        #pragma unroll
        for (int i = 0; i < 8; ++i) a[i] = xs[(r0 + i) * 65 + k];
        #pragma unroll
        for (int j = 0; j < 4; ++j) {
            b[j]     = w1s[(c0 + j) * 65 + k];
            b[4 + j] = w1s[(128 + c0 + j) * 65 + k];
        }
        #pragma unroll
        for (int i = 0; i < 8; ++i)
            #pragma unroll
            for (int j = 0; j < 8; ++j)
                acc[i][j] = fmaf(a[i], b[j], acc[i][j]);
    }

    // PReLU + project onto 4 heads (per-lane partials over this lane's 8 cols)
    float slope = *prelu_a;
    float p[32];
    #pragma unroll
    for (int v = 0; v < 32; ++v) p[v] = 0.f;
    #pragma unroll
    for (int j = 0; j < 8; ++j) {
        int col = (j < 4) ? (c0 + j) : (128 + c0 + j - 4);
        float w0 = w2s[0 * 256 + col], w1v = w2s[1 * 256 + col];
        float w2v = w2s[2 * 256 + col], w3 = w2s[3 * 256 + col];
        #pragma unroll
        for (int i = 0; i < 8; ++i) {
            float h = acc[i][j];
            h = (h >= 0.f) ? h : slope * h;
            p[i * 4 + 0] = fmaf(h, w0,  p[i * 4 + 0]);
            p[i * 4 + 1] = fmaf(h, w1v, p[i * 4 + 1]);
            p[i * 4 + 2] = fmaf(h, w2v, p[i * 4 + 2]);
            p[i * 4 + 3] = fmaf(h, w3,  p[i * 4 + 3]);
        }
    }
    // warp allreduce of the 32 (node,head) partials
    #pragma unroll
    for (int s = 16; s > 0; s >>= 1)
        #pragma unroll
        for (int v = 0; v < 32; ++v)
            p[v] += __shfl_xor_sync(0xffffffffu, p[v], s);

    // lane l owns value l = i*4+h  (static select keeps p in registers)
    float myval = 0.f;
    #pragma unroll
    for (int v = 0; v < 32; ++v) myval = (v == cg) ? p[v] : myval;
    int i = cg >> 2, h = cg & 3;
    int node = m0 + r0 + i;
    if (node < n) g_gate[(size_t)node * 4 + h] = myval;
}

// ------------------------------------------------------------------
// Pass B: feat = relu(x@mw1^T + b1)@mw2^T + b2 ; w = exp(gate)
//         segmented accumulate  out += w*feat,  denom += w
// block = 128 nodes, 256 threads, C tile [128 x 128]
// ------------------------------------------------------------------
#define B_SMEM_FLOATS (128*65 + 128*65 + 128*129 + 128*129 + 8*128 + 32 + 128)
__global__ __launch_bounds__(256) void k_feat(
    const float* __restrict__ x, const int* __restrict__ batch,
    const float* __restrict__ mw1, const float* __restrict__ mb1,
    const float* __restrict__ mw2, const float* __restrict__ mb2,
    float* __restrict__ out, int n)
{
    extern __shared__ float sm[];
    float* xs  = sm;                    // 128*65  = 8320
    float* w1s = sm + 8320;             // 128*65  = 8320
    float* w2s = sm + 16640;            // 128*129 = 16512
    float* t1s = sm + 33152;            // 128*129 = 16512
    float* oac = sm + 49664;            // 8*128   = 1024
    float* dac = sm + 50688;            // 32
    int*  sbat = (int*)(sm + 50720);    // 128 ints

    int tid = threadIdx.x;
    int m0  = blockIdx.x * 128;

    {   // loads
        const float4* x4 = (const float4*)x;
        #pragma unroll
        for (int t = 0; t < 8; ++t) {
            int fid = tid + t * 256;            // < 2048
            int m = fid >> 4, k4 = fid & 15;
            float4 v = make_float4(0.f, 0.f, 0.f, 0.f);
            if (m0 + m < n) v = x4[(size_t)(m0 + m) * 16 + k4];
            float* d = &xs[m * 65 + k4 * 4];
            d[0] = v.x; d[1] = v.y; d[2] = v.z; d[3] = v.w;
        }
        const float4* w14 = (const float4*)mw1;
        #pragma unroll
        for (int t = 0; t < 8; ++t) {
            int fid = tid + t * 256;            // < 2048
            int c = fid >> 4, k4 = fid & 15;
            float4 v = w14[fid];
            float* d = &w1s[c * 65 + k4 * 4];
            d[0] = v.x; d[1] = v.y; d[2] = v.z; d[3] = v.w;
        }
        const float4* w24 = (const float4*)mw2;
        #pragma unroll
        for (int t = 0; t < 16; ++t) {
            int fid = tid + t * 256;            // < 4096
            int c = fid >> 5, k8 = fid & 31;
            float4 v = w24[fid];
            float* d = &w2s[c * 129 + k8 * 4];
            d[0] = v.x; d[1] = v.y; d[2] = v.z; d[3] = v.w;
        }
        if (tid < 128) sbat[tid] = (m0 + tid < n) ? batch[m0 + tid] : -1;
        for (int i = tid; i < 8 * 128; i += 256) oac[i] = 0.f;
        if (tid < 32) dac[tid] = 0.f;
    }
    __syncthreads();

    int rg = tid >> 4, cg = tid & 15;   // warp = 2 row-groups x 16 col-groups
    int r0 = rg * 8, c0 = cg * 4;

    float acc[8][8];
    #pragma unroll
    for (int i = 0; i < 8; ++i)
        #pragma unroll
        for (int j = 0; j < 8; ++j) acc[i][j] = 0.f;

    // GEMM1: t1 = relu(x @ mw1^T + b1), K = 64
    #pragma unroll 8
    for (int k = 0; k < 64; ++k) {
        float a[8], b[8];
        #pragma unroll
        for (int i = 0; i < 8; ++i) a[i] = xs[(r0 + i) * 65 + k];
        #pragma unroll
        for (int j = 0; j < 4; ++j) {
            b[j]     = w1s[(c0 + j) * 65 + k];
            b[4 + j] = w1s[(64 + c0 + j) * 65 + k];
        }
        #pragma unroll
        for (int i = 0; i < 8; ++i)
            #pragma unroll
            for (int j = 0; j < 8; ++j)
                acc[i][j] = fmaf(a[i], b[j], acc[i][j]);
    }
    {   // bias + relu -> t1s
        float b1a[8];
        #pragma unroll
        for (int j = 0; j < 4; ++j) { b1a[j] = mb1[c0 + j]; b1a[4 + j] = mb1[64 + c0 + j]; }
        #pragma unroll
        for (int i = 0; i < 8; ++i)
            #pragma unroll
            for (int j = 0; j < 8; ++j) {
                float v = acc[i][j] + b1a[j];
                v = fmaxf(v, 0.f);
                int col = (j < 4) ? (c0 + j) : (64 + c0 + j - 4);
                t1s[(r0 + i) * 129 + col] = v;
            }
    }
    __syncthreads();

    // GEMM2: feat = t1 @ mw2^T + b2, K = 128
    #pragma unroll
    for (int i = 0; i < 8; ++i)
        #pragma unroll
        for (int j = 0; j < 8; ++j) acc[i][j] = 0.f;
    #pragma unroll 8
    for (int k = 0; k < 128; ++k) {
        float a[8], b[8];
        #pragma unroll
        for (int i = 0; i < 8; ++i) a[i] = t1s[(r0 + i) * 129 + k];
        #pragma unroll
        for (int j = 0; j < 4; ++j) {
            b[j]     = w2s[(c0 + j) * 129 + k];
            b[4 + j] = w2s[(64 + c0 + j) * 129 + k];
        }
        #pragma unroll
        for (int i = 0; i < 8; ++i)
            #pragma unroll
            for (int j = 0; j < 8; ++j)
                acc[i][j] = fmaf(a[i], b[j], acc[i][j]);
    }
    float b2a[8];
    #pragma unroll
    for (int j = 0; j < 4; ++j) { b2a[j] = mb2[c0 + j]; b2a[4 + j] = mb2[64 + c0 + j]; }

    // ---- epilogue: segmented weighted accumulation (batch is sorted) ----
    int hA = cg >> 3;       // head of cols c0..c0+3    (0 or 1)
    int hB = 2 + hA;        // head of cols 64+c0..+3   (2 or 3)
    bool dd = ((cg & 7) == 0);  // designated denom accumulator for (hA,hB)
    int seg_base = sbat[0];

    float av[8];
    #pragma unroll
    for (int v = 0; v < 8; ++v) av[v] = 0.f;
    float dA = 0.f, dB = 0.f;
    int cur = -1;

    #pragma unroll
    for (int i = 0; i < 8; ++i) {
        int m = r0 + i;
        int s = sbat[m];
        if (s >= 0) {
            if (s != cur) {
                if (cur >= 0) {   // flush previous run
                    int loc = cur - seg_base;
                    if (loc < MAXLOC) {
                        #pragma unroll
                        for (int j = 0; j < 4; ++j) {
                            atomicAdd(&oac[loc * 128 + c0 + j],      av[j]);
                            atomicAdd(&oac[loc * 128 + 64 + c0 + j], av[4 + j]);
                        }
                        if (dd) { atomicAdd(&dac[loc * 4 + hA], dA);
                                  atomicAdd(&dac[loc * 4 + hB], dB); }
                    } else {
                        #pragma unroll
                        for (int j = 0; j < 4; ++j) {
                            atomicAdd(&out[(size_t)cur * 128 + c0 + j],      av[j]);
                            atomicAdd(&out[(size_t)cur * 128 + 64 + c0 + j], av[4 + j]);
                        }
                        if (dd) { atomicAdd(&g_denom[cur * 4 + hA], dA);
                                  atomicAdd(&g_denom[cur * 4 + hB], dB); }
                    }
                    #pragma unroll
                    for (int v = 0; v < 8; ++v) av[v] = 0.f;
                    dA = 0.f; dB = 0.f;
                }
                cur = s;
            }
            int node = m0 + m;
            float wA = expf(fminf(g_gate[(size_t)node * 4 + hA], 60.f));
            float wB = expf(fminf(g_gate[(size_t)node * 4 + hB], 60.f));
            #pragma unroll
            for (int j = 0; j < 4; ++j) {
                av[j]     = fmaf(wA, acc[i][j]     + b2a[j],     av[j]);
                av[4 + j] = fmaf(wB, acc[i][4 + j] + b2a[4 + j], av[4 + j]);
            }
            if (dd) { dA += wA; dB += wB; }
        }
    }
    if (cur >= 0) {   // final flush
        int loc = cur - seg_base;
        if (loc < MAXLOC) {
            #pragma unroll
            for (int j = 0; j < 4; ++j) {
                atomicAdd(&oac[loc * 128 + c0 + j],      av[j]);
                atomicAdd(&oac[loc * 128 + 64 + c0 + j], av[4 + j]);
            }
            if (dd) { atomicAdd(&dac[loc * 4 + hA], dA);
                      atomicAdd(&dac[loc * 4 + hB], dB); }
        } else {
            #pragma unroll
            for (int j = 0; j < 4; ++j) {
                atomicAdd(&out[(size_t)cur * 128 + c0 + j],      av[j]);
                atomicAdd(&out[(size_t)cur * 128 + 64 + c0 + j], av[4 + j]);
            }
            if (dd) { atomicAdd(&g_denom[cur * 4 + hA], dA);
                      atomicAdd(&g_denom[cur * 4 + hB], dB); }
        }
    }
    __syncthreads();

    // block-level flush of the smem segment accumulators
    int lastm = n - m0; if (lastm > 128) lastm = 128; lastm -= 1;
    int loc_cnt = sbat[lastm] - seg_base + 1;
    if (loc_cnt > MAXLOC) loc_cnt = MAXLOC;
    for (int idx = tid; idx < loc_cnt * 128; idx += 256) {
        int loc = idx >> 7, ch = idx & 127;
        atomicAdd(&out[(size_t)(seg_base + loc) * 128 + ch], oac[idx]);
    }
    if (tid < loc_cnt * 4)
        atomicAdd(&g_denom[(seg_base + (tid >> 2)) * 4 + (tid & 3)], dac[tid]);
}

// ------------------------------------------------------------------
// Pass C: divide by per-(segment,head) denominator
// ------------------------------------------------------------------
__global__ void k_div(float* __restrict__ out) {
    int i = blockIdx.x * blockDim.x + threadIdx.x;
    if (i < SEGS * MID) {
        int s = i >> 7, h = (i & 127) >> 5;
        out[i] = out[i] / (g_denom[s * 4 + h] + 1e-16f);
    }
}

// ------------------------------------------------------------------
extern "C" void kernel_launch(void* const* d_in, const int* in_sizes, int n_in,
                              void* d_out, int out_size)
{
    const float* x    = (const float*)d_in[0];
    const int*   bat  = (const int*)d_in[1];
    // d_in[2] = num_segments (unused, fixed 1024)
    const float* gw1  = (const float*)d_in[3];
    const float* pa   = (const float*)d_in[4];
    const float* gw2  = (const float*)d_in[5];
    const float* mw1  = (const float*)d_in[6];
    const float* mb1  = (const float*)d_in[7];
    const float* mw2  = (const float*)d_in[8];
    const float* mb2  = (const float*)d_in[9];
    float* out = (float*)d_out;
    int n = in_sizes[0] / IN_CH;

    const int a_smem = A_SMEM_FLOATS * 4;   // 87,296 B
    const int b_smem = B_SMEM_FLOATS * 4;   // 203,392 B
    cudaFuncSetAttribute(k_gate, cudaFuncAttributeMaxDynamicSharedMemorySize, a_smem);
    cudaFuncSetAttribute(k_feat, cudaFuncAttributeMaxDynamicSharedMemorySize, b_smem);

    k_init<<<(SEGS * MID + 255) / 256, 256>>>(out);
    k_gate<<<(n + 63) / 64, 256, a_smem>>>(x, gw1, gw2, pa, n);
    k_feat<<<(n + 127) / 128, 256, b_smem>>>(x, bat, mw1, mb1, mw2, mb2, out, n);
    k_div<<<(SEGS * MID + 255) / 256, 256>>>(out);
}

// round 11
// speedup vs baseline: 1.0004x; 1.0004x over previous
#include <cuda_runtime.h>
#include <math.h>

#define IN_CH   64
#define MID     128      // OUT_CH*HEADS
#define GH      256      // HEADS*IN_CH (gate hidden)
#define HEADS   4
#define SEGS    1024
#define MAXN    500000
#define MAXLOC  8

// scratch (static device globals — no runtime allocation)
__device__ float g_gate[(size_t)MAXN * HEADS];   // 8 MB
__device__ float g_denom[SEGS * HEADS];

// ------------------------------------------------------------------
// init: zero output accumulator and denominators
// ------------------------------------------------------------------
__global__ void k_init(float* __restrict__ out) {
    int i = blockIdx.x * blockDim.x + threadIdx.x;
    if (i < SEGS * MID)   out[i] = 0.f;
    if (i < SEGS * HEADS) g_denom[i] = 0.f;
}

// ------------------------------------------------------------------
// Pass A: gate[N,4] = prelu(x @ gw1^T) @ gw2^T
// block = 64 nodes, 256 threads, C tile [64 x 256] (8x8 micro per thread)
// smem: xs[64][65] | w1[256][65] | w2[4*256]
// ------------------------------------------------------------------
#define A_SMEM_FLOATS (64*65 + 256*65 + 1024)
__global__ __launch_bounds__(256) void k_gate(
    const float* __restrict__ x, const float* __restrict__ gw1,
    const float* __restrict__ gw2, const float* __restrict__ prelu_a, int n)
{
    extern __shared__ float sm[];
    float* xs  = sm;                    // 64*65 = 4160
    float* w1s = sm + 4160;             // 256*65 = 16640
    float* w2s = sm + 4160 + 16640;     // 1024

    int tid = threadIdx.x;
    int m0  = blockIdx.x * 64;

    {   // x tile (zero padded)
        const float4* x4 = (const float4*)x;
        #pragma unroll
        for (int t = 0; t < 4; ++t) {
            int fid = tid + t * 256;            // < 1024
            int m = fid >> 4, k4 = fid & 15;
            float4 v = make_float4(0.f, 0.f, 0.f, 0.f);
            if (m0 + m < n) v = x4[(size_t)(m0 + m) * 16 + k4];
            float* d = &xs[m * 65 + k4 * 4];
            d[0] = v.x; d[1] = v.y; d[2] = v.z; d[3] = v.w;
        }
        const float4* w14 = (const float4*)gw1;
        #pragma unroll
        for (int t = 0; t < 16; ++t) {
            int fid = tid + t * 256;            // < 4096
            int c = fid >> 4, k4 = fid & 15;
            float4 v = w14[fid];
            float* d = &w1s[c * 65 + k4 * 4];
            d[0] = v.x; d[1] = v.y; d[2] = v.z; d[3] = v.w;
        }
        ((float4*)w2s)[tid] = ((const float4*)gw2)[tid];  // 256 float4 = 1024 f
    }
    __syncthreads();

    int rg = tid >> 5, cg = tid & 31;   // warp = one row-group, lanes span cols
    int r0 = rg * 8, c0 = cg * 4;

    float acc[8][8];
    #pragma unroll
    for (int i = 0; i < 8; ++i)
        #pragma unroll
        for (int j = 0; j < 8; ++j) acc[i][j] = 0.f;

    #pragma unroll 8
    for (int k = 0; k < 64; ++k) {
        float a[8], b[8];
        #pragma unroll
        for (int i = 0; i < 8; ++i) a[i] = xs[(r0 + i) * 65 + k];
        #pragma unroll
        for (int j = 0; j < 4; ++j) {
            b[j]     = w1s[(c0 + j) * 65 + k];
            b[4 + j] = w1s[(128 + c0 + j) * 65 + k];
        }
        #pragma unroll
        for (int i = 0; i < 8; ++i)
            #pragma unroll
            for (int j = 0; j < 8; ++j)
                acc[i][j] = fmaf(a[i], b[j], acc[i][j]);
    }

    // PReLU + project onto 4 heads (per-lane partials over this lane's 8 cols)
    float slope = *prelu_a;
    float p[32];
    #pragma unroll
    for (int v = 0; v < 32; ++v) p[v] = 0.f;
    #pragma unroll
    for (int j = 0; j < 8; ++j) {
        int col = (j < 4) ? (c0 + j) : (128 + c0 + j - 4);
        float w0 = w2s[0 * 256 + col], w1v = w2s[1 * 256 + col];
        float w2v = w2s[2 * 256 + col], w3 = w2s[3 * 256 + col];
        #pragma unroll
        for (int i = 0; i < 8; ++i) {
            float h = acc[i][j];
            h = (h >= 0.f) ? h : slope * h;
            p[i * 4 + 0] = fmaf(h, w0,  p[i * 4 + 0]);
            p[i * 4 + 1] = fmaf(h, w1v, p[i * 4 + 1]);
            p[i * 4 + 2] = fmaf(h, w2v, p[i * 4 + 2]);
            p[i * 4 + 3] = fmaf(h, w3,  p[i * 4 + 3]);
        }
    }
    // warp allreduce of the 32 (node,head) partials
    #pragma unroll
    for (int s = 16; s > 0; s >>= 1)
        #pragma unroll
        for (int v = 0; v < 32; ++v)
            p[v] += __shfl_xor_sync(0xffffffffu, p[v], s);

    // lane l owns value l = i*4+h  (static select keeps p in registers)
    float myval = 0.f;
    #pragma unroll
    for (int v = 0; v < 32; ++v) myval = (v == cg) ? p[v] : myval;
    int i = cg >> 2, h = cg & 3;
    int node = m0 + r0 + i;
    if (node < n) g_gate[(size_t)node * 4 + h] = myval;
}

// ------------------------------------------------------------------
// Pass B: feat = relu(x@mw1^T + b1)@mw2^T + b2 ; w = exp(gate)
//         segmented accumulate  out += w*feat,  denom += w
// block = 128 nodes, 256 threads, C tile [128 x 128]
// ------------------------------------------------------------------
#define B_SMEM_FLOATS (128*65 + 128*65 + 128*129 + 128*129 + 8*128 + 32 + 128)
__global__ __launch_bounds__(256) void k_feat(
    const float* __restrict__ x, const int* __restrict__ batch,
    const float* __restrict__ mw1, const float* __restrict__ mb1,
    const float* __restrict__ mw2, const float* __restrict__ mb2,
    float* __restrict__ out, int n)
{
    extern __shared__ float sm[];
    float* xs  = sm;                    // 128*65  = 8320
    float* w1s = sm + 8320;             // 128*65  = 8320
    float* w2s = sm + 16640;            // 128*129 = 16512
    float* t1s = sm + 33152;            // 128*129 = 16512
    float* oac = sm + 49664;            // 8*128   = 1024
    float* dac = sm + 50688;            // 32
    int*  sbat = (int*)(sm + 50720);    // 128 ints

    int tid = threadIdx.x;
    int m0  = blockIdx.x * 128;

    {   // loads
        const float4* x4 = (const float4*)x;
        #pragma unroll
        for (int t = 0; t < 8; ++t) {
            int fid = tid + t * 256;            // < 2048
            int m = fid >> 4, k4 = fid & 15;
            float4 v = make_float4(0.f, 0.f, 0.f, 0.f);
            if (m0 + m < n) v = x4[(size_t)(m0 + m) * 16 + k4];
            float* d = &xs[m * 65 + k4 * 4];
            d[0] = v.x; d[1] = v.y; d[2] = v.z; d[3] = v.w;
        }
        const float4* w14 = (const float4*)mw1;
        #pragma unroll
        for (int t = 0; t < 8; ++t) {
            int fid = tid + t * 256;            // < 2048
            int c = fid >> 4, k4 = fid & 15;
            float4 v = w14[fid];
            float* d = &w1s[c * 65 + k4 * 4];
            d[0] = v.x; d[1] = v.y; d[2] = v.z; d[3] = v.w;
        }
        const float4* w24 = (const float4*)mw2;
        #pragma unroll
        for (int t = 0; t < 16; ++t) {
            int fid = tid + t * 256;            // < 4096
            int c = fid >> 5, k8 = fid & 31;
            float4 v = w24[fid];
            float* d = &w2s[c * 129 + k8 * 4];
            d[0] = v.x; d[1] = v.y; d[2] = v.z; d[3] = v.w;
        }
        if (tid < 128) sbat[tid] = (m0 + tid < n) ? batch[m0 + tid] : -1;
        for (int i = tid; i < 8 * 128; i += 256) oac[i] = 0.f;
        if (tid < 32) dac[tid] = 0.f;
    }
    __syncthreads();

    int rg = tid >> 4, cg = tid & 15;   // warp = 2 row-groups x 16 col-groups
    int r0 = rg * 8, c0 = cg * 4;

    float acc[8][8];
    #pragma unroll
    for (int i = 0; i < 8; ++i)
        #pragma unroll
        for (int j = 0; j < 8; ++j) acc[i][j] = 0.f;

    // GEMM1: t1 = relu(x @ mw1^T + b1), K = 64
    #pragma unroll 8
    for (int k = 0; k < 64; ++k) {
        float a[8], b[8];
        #pragma unroll
        for (int i = 0; i < 8; ++i) a[i] = xs[(r0 + i) * 65 + k];
        #pragma unroll
        for (int j = 0; j < 4; ++j) {
            b[j]     = w1s[(c0 + j) * 65 + k];
            b[4 + j] = w1s[(64 + c0 + j) * 65 + k];
        }
        #pragma unroll
        for (int i = 0; i < 8; ++i)
            #pragma unroll
            for (int j = 0; j < 8; ++j)
                acc[i][j] = fmaf(a[i], b[j], acc[i][j]);
    }
    {   // bias + relu -> t1s
        float b1a[8];
        #pragma unroll
        for (int j = 0; j < 4; ++j) { b1a[j] = mb1[c0 + j]; b1a[4 + j] = mb1[64 + c0 + j]; }
        #pragma unroll
        for (int i = 0; i < 8; ++i)
            #pragma unroll
            for (int j = 0; j < 8; ++j) {
                float v = acc[i][j] + b1a[j];
                v = fmaxf(v, 0.f);
                int col = (j < 4) ? (c0 + j) : (64 + c0 + j - 4);
                t1s[(r0 + i) * 129 + col] = v;
            }
    }
    __syncthreads();

    // GEMM2: feat = t1 @ mw2^T + b2, K = 128
    #pragma unroll
    for (int i = 0; i < 8; ++i)
        #pragma unroll
        for (int j = 0; j < 8; ++j) acc[i][j] = 0.f;
    #pragma unroll 8
    for (int k = 0; k < 128; ++k) {
        float a[8], b[8];
        #pragma unroll
        for (int i = 0; i < 8; ++i) a[i] = t1s[(r0 + i) * 129 + k];
        #pragma unroll
        for (int j = 0; j < 4; ++j) {
            b[j]     = w2s[(c0 + j) * 129 + k];
            b[4 + j] = w2s[(64 + c0 + j) * 129 + k];
        }
        #pragma unroll
        for (int i = 0; i < 8; ++i)
            #pragma unroll
            for (int j = 0; j < 8; ++j)
                acc[i][j] = fmaf(a[i], b[j], acc[i][j]);
    }
    float b2a[8];
    #pragma unroll
    for (int j = 0; j < 4; ++j) { b2a[j] = mb2[c0 + j]; b2a[4 + j] = mb2[64 + c0 + j]; }

    // ---- epilogue: segmented weighted accumulation (batch is sorted) ----
    int hA = cg >> 3;       // head of cols c0..c0+3    (0 or 1)
    int hB = 2 + hA;        // head of cols 64+c0..+3   (2 or 3)
    bool dd = ((cg & 7) == 0);  // designated denom accumulator for (hA,hB)
    int seg_base = sbat[0];

    float av[8];
    #pragma unroll
    for (int v = 0; v < 8; ++v) av[v] = 0.f;
    float dA = 0.f, dB = 0.f;
    int cur = -1;

    #pragma unroll
    for (int i = 0; i < 8; ++i) {
        int m = r0 + i;
        int s = sbat[m];
        if (s >= 0) {
            if (s != cur) {
                if (cur >= 0) {   // flush previous run
                    int loc = cur - seg_base;
                    if (loc < MAXLOC) {
                        #pragma unroll
                        for (int j = 0; j < 4; ++j) {
                            atomicAdd(&oac[loc * 128 + c0 + j],      av[j]);
                            atomicAdd(&oac[loc * 128 + 64 + c0 + j], av[4 + j]);
                        }
                        if (dd) { atomicAdd(&dac[loc * 4 + hA], dA);
                                  atomicAdd(&dac[loc * 4 + hB], dB); }
                    } else {
                        #pragma unroll
                        for (int j = 0; j < 4; ++j) {
                            atomicAdd(&out[(size_t)cur * 128 + c0 + j],      av[j]);
                            atomicAdd(&out[(size_t)cur * 128 + 64 + c0 + j], av[4 + j]);
                        }
                        if (dd) { atomicAdd(&g_denom[cur * 4 + hA], dA);
                                  atomicAdd(&g_denom[cur * 4 + hB], dB); }
                    }
                    #pragma unroll
                    for (int v = 0; v < 8; ++v) av[v] = 0.f;
                    dA = 0.f; dB = 0.f;
                }
                cur = s;
            }
            int node = m0 + m;
            float wA = expf(fminf(g_gate[(size_t)node * 4 + hA], 60.f));
            float wB = expf(fminf(g_gate[(size_t)node * 4 + hB], 60.f));
            #pragma unroll
            for (int j = 0; j < 4; ++j) {
                av[j]     = fmaf(wA, acc[i][j]     + b2a[j],     av[j]);
                av[4 + j] = fmaf(wB, acc[i][4 + j] + b2a[4 + j], av[4 + j]);
            }
            if (dd) { dA += wA; dB += wB; }
        }
    }
    if (cur >= 0) {   // final flush
        int loc = cur - seg_base;
        if (loc < MAXLOC) {
            #pragma unroll
            for (int j = 0; j < 4; ++j) {
                atomicAdd(&oac[loc * 128 + c0 + j],      av[j]);
                atomicAdd(&oac[loc * 128 + 64 + c0 + j], av[4 + j]);
            }
            if (dd) { atomicAdd(&dac[loc * 4 + hA], dA);
                      atomicAdd(&dac[loc * 4 + hB], dB); }
        } else {
            #pragma unroll
            for (int j = 0; j < 4; ++j) {
                atomicAdd(&out[(size_t)cur * 128 + c0 + j],      av[j]);
                atomicAdd(&out[(size_t)cur * 128 + 64 + c0 + j], av[4 + j]);
            }
            if (dd) { atomicAdd(&g_denom[cur * 4 + hA], dA);
                      atomicAdd(&g_denom[cur * 4 + hB], dB); }
        }
    }
    __syncthreads();

    // block-level flush of the smem segment accumulators
    int lastm = n - m0; if (lastm > 128) lastm = 128; lastm -= 1;
    int loc_cnt = sbat[lastm] - seg_base + 1;
    if (loc_cnt > MAXLOC) loc_cnt = MAXLOC;
    for (int idx = tid; idx < loc_cnt * 128; idx += 256) {
        int loc = idx >> 7, ch = idx & 127;
        atomicAdd(&out[(size_t)(seg_base + loc) * 128 + ch], oac[idx]);
    }
    if (tid < loc_cnt * 4)
        atomicAdd(&g_denom[(seg_base + (tid >> 2)) * 4 + (tid & 3)], dac[tid]);
}

// ------------------------------------------------------------------
// Pass C: divide by per-(segment,head) denominator
// ------------------------------------------------------------------
__global__ void k_div(float* __restrict__ out) {
    int i = blockIdx.x * blockDim.x + threadIdx.x;
    if (i < SEGS * MID) {
        int s = i >> 7, h = (i & 127) >> 5;
        out[i] = out[i] / (g_denom[s * 4 + h] + 1e-16f);
    }
}

// ------------------------------------------------------------------
extern "C" void kernel_launch(void* const* d_in, const int* in_sizes, int n_in,
                              void* d_out, int out_size)
{
    const float* x    = (const float*)d_in[0];
    const int*   bat  = (const int*)d_in[1];
    // d_in[2] = num_segments (unused, fixed 1024)
    const float* gw1  = (const float*)d_in[3];
    const float* pa   = (const float*)d_in[4];
    const float* gw2  = (const float*)d_in[5];
    const float* mw1  = (const float*)d_in[6];
    const float* mb1  = (const float*)d_in[7];
    const float* mw2  = (const float*)d_in[8];
    const float* mb2  = (const float*)d_in[9];
    float* out = (float*)d_out;
    int n = in_sizes[0] / IN_CH;

    const int a_smem = A_SMEM_FLOATS * 4;   // 87,296 B
    const int b_smem = B_SMEM_FLOATS * 4;   // 203,392 B
    cudaFuncSetAttribute(k_gate, cudaFuncAttributeMaxDynamicSharedMemorySize, a_smem);
    cudaFuncSetAttribute(k_feat, cudaFuncAttributeMaxDynamicSharedMemorySize, b_smem);

    k_init<<<(SEGS * MID + 255) / 256, 256>>>(out);
    k_gate<<<(n + 63) / 64, 256, a_smem>>>(x, gw1, gw2, pa, n);
    k_feat<<<(n + 127) / 128, 256, b_smem>>>(x, bat, mw1, mb1, mw2, mb2, out, n);
    k_div<<<(SEGS * MID + 255) / 256, 256>>>(out);
}